// round 9
// baseline (speedup 1.0000x reference)
#include <cuda_runtime.h>
#include <cuda_bf16.h>

#define Hcst   1024
#define Dcst   128
#define TPcst  48
#define NBcst  384
#define Ecst   16384
#define EHcst  17408
#define OUTHALF 196608
#define MAXDEG 64

typedef unsigned long long u64;

// ---------------- device scratch ----------------
__device__ u64      g_Xh[NBcst*Hcst];     // 3.1 MB bf16x4 taps
__device__ int      g_cursor[Hcst];
__device__ float    g_deg[Hcst];
__device__ int      g_degi[Hcst];
__device__ unsigned g_pkT[MAXDEG*Hcst];   // transposed edges: [e][v]
__device__ float    g_rowsum[Hcst];
__device__ float    g_S[4*Hcst];
__device__ int      g_invgrp[Hcst];
__device__ float    g_WW1[4*Dcst];
__device__ float    g_bb1[Dcst];
__device__ float    g_hpro[4*48*Dcst];    // 98 KB
__device__ float    g_wpro[4*7*Dcst];     // 14 KB

// ---------------- helpers ----------------
__device__ __forceinline__ u64 pk2(float lo, float hi) {
    u64 r; asm("mov.b64 %0,{%1,%2};" : "=l"(r) : "f"(lo), "f"(hi)); return r;
}
__device__ __forceinline__ void upk2(u64 v, float& lo, float& hi) {
    asm("mov.b64 {%0,%1},%2;" : "=f"(lo), "=f"(hi) : "l"(v));
}
__device__ __forceinline__ u64 fma2(u64 a, u64 b, u64 c) {
    u64 d; asm("fma.rn.f32x2 %0,%1,%2,%3;" : "=l"(d) : "l"(a), "l"(b), "l"(c)); return d;
}
__device__ __forceinline__ u64 pkbf4(float a, float b, float c, float d) {
    return (u64)__bfloat16_as_ushort(__float2bfloat16(a))
         | ((u64)__bfloat16_as_ushort(__float2bfloat16(b)) << 16)
         | ((u64)__bfloat16_as_ushort(__float2bfloat16(c)) << 32)
         | ((u64)__bfloat16_as_ushort(__float2bfloat16(d)) << 48);
}

// ================= k1 : degree/prep + vectorized X4 transpose =================
__global__ void __launch_bounds__(512) k1(const void* ed, const void* ns,
        const float* x, const float* tvw, const float* tvb, const float* W1) {
    __shared__ int cnt[Hcst];
    __shared__ int sflag;
    int t = threadIdx.x, blk = blockIdx.x;
    if (blk == 0) {
        if (t == 0) sflag = 1;
        __syncthreads();
        if (t < 64) { if (((const int*)ed)[2*t+1] != 0) atomicAnd(&sflag, 0); }
        cnt[t] = 1; cnt[t+512] = 1;      // self loops
        __syncthreads();
        int f = sflag;
        #pragma unroll 4
        for (int i = t; i < Ecst; i += 512) {
            int d = f ? (int)((const long long*)ed)[2L*i+1] : ((const int*)ed)[2*i+1];
            atomicAdd(&cnt[d], 1);
        }
        __syncthreads();
        #pragma unroll
        for (int r = 0; r < 2; r++) {
            int v = t + r*512;
            int c = cnt[v];
            g_deg[v] = (float)c; g_degi[v] = c; g_cursor[v] = 0;
        }
    } else if (blk == 1) {
        if (t == 0) sflag = 1;
        __syncthreads();
        if (t < 64) { if (((const int*)ns)[2*t+1] != 0) atomicAnd(&sflag, 0); }
        __syncthreads();
        int f = sflag;
        #pragma unroll
        for (int r = 0; r < 2; r++) {
            int i = t + r*512;
            int v = f ? (int)((const long long*)ns)[i] : ((const int*)ns)[i];
            g_invgrp[v] = i >> 8;
        }
    } else if (blk == 2) {
        int k = t >> 7, e = t & 127;
        float acc = 0.f;
        for (int d = 0; d < Dcst; d++) acc += tvw[d*4 + k] * W1[d*Dcst + e];
        g_WW1[k*Dcst + e] = acc;
        if (t < 128) {
            float bsum = 0.f;
            for (int d = 0; d < Dcst; d++) bsum += tvb[d] * W1[d*Dcst + t];
            g_bb1[t] = bsum;
        }
    } else if (blk == 3) {
        #pragma unroll
        for (int i = t; i < 4*Hcst; i += 512) g_S[i] = 0.f;
        #pragma unroll
        for (int i = t; i < Hcst; i += 512) g_rowsum[i] = 0.f;
    } else {
        // X4 transpose -> bf16x4, vectorized: 2 b's per block, 4 v's per thread
        int sub = t >> 8, tl = t & 255;
        int b = (blk - 4)*2 + sub, n = b / TPcst, tp = b % TPcst;
        const float4* xb = (const float4*)(x + ((long)(n*192 + tp*4))*Hcst);
        float4 r0 = xb[tl], r1 = xb[256+tl], r2 = xb[512+tl], r3 = xb[768+tl];
        ulonglong2 w0, w1;
        w0.x = pkbf4(r0.x, r1.x, r2.x, r3.x);
        w0.y = pkbf4(r0.y, r1.y, r2.y, r3.y);
        w1.x = pkbf4(r0.z, r1.z, r2.z, r3.z);
        w1.y = pkbf4(r0.w, r1.w, r2.w, r3.w);
        ulonglong2* dst = (ulonglong2*)(g_Xh + (long)b*Hcst + tl*4);
        dst[0] = w0;
        dst[1] = w1;
    }
}

// ================= k2 : edge fill + projection tables =================
__global__ void __launch_bounds__(512) k2(const void* ed,
        const float* tcw, const float* hemb, const float* wemb) {
    __shared__ union {
        int dummy;
        struct { float tcwS[8][516]; float embH[48][129]; float embW[7][129]; } p;
    } sm;
    __shared__ int sflag;
    int t = threadIdx.x, blk = blockIdx.x;
    if (blk < 34) {
        // fill pkT (+rowsum, +S): 34 x 512 = 17408
        if (t == 0) sflag = 1;
        __syncthreads();
        if (t < 64) { if (((const int*)ed)[2*t+1] != 0) atomicAnd(&sflag, 0); }
        __syncthreads();
        int f = sflag;
        int i = blk*512 + t;
        int s, d;
        if (i < Ecst) {
            if (f) { s = (int)((const long long*)ed)[2L*i]; d = (int)((const long long*)ed)[2L*i+1]; }
            else   { s = ((const int*)ed)[2*i];             d = ((const int*)ed)[2*i+1]; }
        } else s = d = i - Ecst;
        float w = rsqrtf(g_deg[s]*g_deg[d]);
        int local = atomicAdd(&g_cursor[d], 1);
        unsigned cb = (unsigned)__bfloat16_as_ushort(__float2bfloat16(w));
        if (local < MAXDEG)
            g_pkT[local*Hcst + d] = (unsigned)s | (cb << 16);
        atomicAdd(&g_rowsum[d], w);
        atomicAdd(&g_S[g_invgrp[d]*Hcst + s], w * (1.f/256.f));
    } else {
        // projection tables: 16 blocks, 8 d's each
        int d0 = (blk - 34)*8;
        for (int i = t; i < 8*512; i += 512)
            sm.p.tcwS[i >> 9][i & 511] = tcw[(long)(d0 + (i >> 9))*512 + (i & 511)];
        for (int i = t; i < 48*128; i += 512)
            sm.p.embH[i >> 7][i & 127] = hemb[i];
        for (int i = t; i < 7*128; i += 512)
            sm.p.embW[i >> 7][i & 127] = wemb[i];
        __syncthreads();
        int dl = t & 7;
        #pragma unroll
        for (int pass = 0; pass < 4; pass++) {
            int pair = (t >> 3) + pass*64;
            if (pair >= 220) continue;
            const float* er; float* dst; int k, r;
            if (pair < 192) { k = pair / 48; r = pair % 48; er = sm.p.embH[r]; dst = g_hpro + (k*48 + r)*Dcst; }
            else { int q = pair - 192; k = q / 7; r = q % 7; er = sm.p.embW[r]; dst = g_wpro + (k*7 + r)*Dcst; }
            float acc = 0.f;
            #pragma unroll 8
            for (int c = 0; c < 128; c++)
                acc += er[c] * sm.p.tcwS[dl][4*c + k];
            dst[d0 + dl] = acc;
        }
    }
}

// ================= k3 : per-b gather + token + epilogue =================
__global__ void __launch_bounds__(256, 3) k3(const void* xm, const float* tcb,
        const float* b1, const float* W2, const float* b2, float* out) {
    __shared__ union { u64 Xh[Hcst]; u64 Acc[256][4]; } sm;      // 8 KB
    __shared__ float      sY0[Hcst], sY1[Hcst], sY2[Hcst], sY3[Hcst]; // 16 KB
    __shared__ ulonglong2 sSI[Hcst];     // 16 KB
    __shared__ u64        sRSp[512];     // 4 KB
    __shared__ ulonglong2 sGM[128];      // 2 KB
    __shared__ int        sIdxH[4], sIdxW[4], sflag;

    int t = threadIdx.x, b = blockIdx.x;
    int n = b / TPcst, tp = b % TPcst;

    if (t == 0) sflag = 1;
    __syncthreads();
    if (t < 64) { if (((const int*)xm)[2*t+1] != 0) atomicAnd(&sflag, 0); }

    // prefetch S / rowsum into registers (latency hidden under gather)
    float S0[4], S1[4], S2[4], S3[4];
    #pragma unroll
    for (int it = 0; it < 4; it++) {
        int i = t + it*256;
        S0[it] = g_S[i]; S1[it] = g_S[Hcst+i]; S2[it] = g_S[2*Hcst+i]; S3[it] = g_S[3*Hcst+i];
    }
    float r0[2], r1[2];
    #pragma unroll
    for (int it = 0; it < 2; it++) {
        int vp = t + it*256;
        r0[it] = g_rowsum[2*vp]; r1[it] = g_rowsum[2*vp+1];
    }
    // taps into smem
    #pragma unroll
    for (int it = 0; it < 4; it++) {
        int i = t + it*256;
        sm.Xh[i] = g_Xh[(long)b*Hcst + i];
    }
    __syncthreads();
    if (t < 8) {
        int k = t & 3, isH = t >> 2;
        long base = ((long)(n*192 + tp*4 + k))*2 + isH;
        int v = sflag ? (int)((const long long*)xm)[base] : ((const int*)xm)[base];
        if (isH) sIdxH[k] = v; else sIdxW[k] = v;
    }

    // ---- gather: coalesced pkT reads, smem taps, unroll 2 ----
    #pragma unroll
    for (int rep = 0; rep < 4; rep++) {
        int v = rep*256 + t;
        int dv = g_degi[v];
        float a0=0.f, a1=0.f, a2=0.f, a3=0.f;
        int e = 0;
        for (; e + 2 <= dv; e += 2) {
            unsigned p0 = g_pkT[e*Hcst + v];
            unsigned p1 = g_pkT[(e+1)*Hcst + v];
            u64 xv0 = sm.Xh[p0 & 1023u];
            u64 xv1 = sm.Xh[p1 & 1023u];
            float w0 = __uint_as_float(p0 & 0xFFFF0000u);
            float w1 = __uint_as_float(p1 & 0xFFFF0000u);
            a0 += w0*__uint_as_float((unsigned)(xv0 & 0xFFFFu) << 16)
                + w1*__uint_as_float((unsigned)(xv1 & 0xFFFFu) << 16);
            a1 += w0*__uint_as_float((unsigned)xv0 & 0xFFFF0000u)
                + w1*__uint_as_float((unsigned)xv1 & 0xFFFF0000u);
            a2 += w0*__uint_as_float((unsigned)((xv0 >> 32) & 0xFFFFu) << 16)
                + w1*__uint_as_float((unsigned)((xv1 >> 32) & 0xFFFFu) << 16);
            a3 += w0*__uint_as_float((unsigned)(xv0 >> 48) << 16)
                + w1*__uint_as_float((unsigned)(xv1 >> 48) << 16);
        }
        if (e < dv) {
            unsigned p = g_pkT[e*Hcst + v];
            u64 xv = sm.Xh[p & 1023u];
            float w = __uint_as_float(p & 0xFFFF0000u);
            a0 += w*__uint_as_float((unsigned)(xv & 0xFFFFu) << 16);
            a1 += w*__uint_as_float((unsigned)xv & 0xFFFF0000u);
            a2 += w*__uint_as_float((unsigned)((xv >> 32) & 0xFFFFu) << 16);
            a3 += w*__uint_as_float((unsigned)(xv >> 48) << 16);
        }
        sY0[v] = a0; sY1[v] = a1; sY2[v] = a2; sY3[v] = a3;
    }
    // commit prefetched S / rowsum
    #pragma unroll
    for (int it = 0; it < 4; it++) {
        int i = t + it*256;
        ulonglong2 e;
        e.x = pk2(S0[it], S1[it]);
        e.y = pk2(S2[it], S3[it]);
        sSI[i] = e;
    }
    #pragma unroll
    for (int it = 0; it < 2; it++)
        sRSp[t + it*256] = pk2(r0[it], r1[it]);
    __syncthreads();

    // ---- token loop ----
    int dA = t & 63, dB = dA + 64;
    int q  = t >> 6;
    u64 W0A = pk2(g_WW1[dA],     g_WW1[dA]);
    u64 W1A = pk2(g_WW1[128+dA], g_WW1[128+dA]);
    u64 W2A = pk2(g_WW1[256+dA], g_WW1[256+dA]);
    u64 W3A = pk2(g_WW1[384+dA], g_WW1[384+dA]);
    u64 BBA = pk2(g_bb1[dA],     g_bb1[dA]);
    u64 B1A = pk2(b1[dA],        b1[dA]);
    u64 W0B = pk2(g_WW1[dB],     g_WW1[dB]);
    u64 W1B = pk2(g_WW1[128+dB], g_WW1[128+dB]);
    u64 W2B = pk2(g_WW1[256+dB], g_WW1[256+dB]);
    u64 W3B = pk2(g_WW1[384+dB], g_WW1[384+dB]);
    u64 BBB = pk2(g_bb1[dB],     g_bb1[dB]);
    u64 B1B = pk2(b1[dB],        b1[dB]);
    u64 a01A = 0, a23A = 0, a01B = 0, a23B = 0;
    int vp0 = q*128;
    #pragma unroll 2
    for (int vp = vp0; vp < vp0+128; vp++) {
        u64 yax = *(const u64*)&sY0[2*vp];
        u64 yay = *(const u64*)&sY1[2*vp];
        u64 ybx = *(const u64*)&sY2[2*vp];
        u64 yby = *(const u64*)&sY3[2*vp];
        u64 rsp = sRSp[vp];
        u64 hA = fma2(yax, W0A, B1A);
        hA = fma2(yay, W1A, hA);
        hA = fma2(ybx, W2A, hA);
        hA = fma2(yby, W3A, hA);
        hA = fma2(rsp, BBA, hA);
        u64 hB = fma2(yax, W0B, B1B);
        hB = fma2(yay, W1B, hB);
        hB = fma2(ybx, W2B, hB);
        hB = fma2(yby, W3B, hB);
        hB = fma2(rsp, BBB, hB);
        float ae, ao, be, bo;
        upk2(hA, ae, ao); upk2(hB, be, bo);
        ae = fmaxf(ae, 0.f); ao = fmaxf(ao, 0.f);
        be = fmaxf(be, 0.f); bo = fmaxf(bo, 0.f);
        u64 hAe = pk2(ae, ae), hAo = pk2(ao, ao);
        u64 hBe = pk2(be, be), hBo = pk2(bo, bo);
        ulonglong2 s0 = sSI[2*vp], s1 = sSI[2*vp+1];
        a01A = fma2(s0.x, hAe, a01A); a23A = fma2(s0.y, hAe, a23A);
        a01A = fma2(s1.x, hAo, a01A); a23A = fma2(s1.y, hAo, a23A);
        a01B = fma2(s0.x, hBe, a01B); a23B = fma2(s0.y, hBe, a23B);
        a01B = fma2(s1.x, hBo, a01B); a23B = fma2(s1.y, hBo, a23B);
    }
    __syncthreads();   // Xh no longer needed; safe to overwrite with Acc
    sm.Acc[t][0] = a01A; sm.Acc[t][1] = a23A; sm.Acc[t][2] = a01B; sm.Acc[t][3] = a23B;
    __syncthreads();

    // ---- reduce quarters ----
    if (t < 128) {
        int d = t, lane = d & 63, hi = d >> 6;
        float g0=0.f, g1=0.f, g2=0.f, g3=0.f;
        #pragma unroll
        for (int qq = 0; qq < 4; qq++) {
            float x0, x1;
            upk2(sm.Acc[qq*64+lane][hi*2+0], x0, x1); g0 += x0; g1 += x1;
            upk2(sm.Acc[qq*64+lane][hi*2+1], x0, x1); g2 += x0; g3 += x1;
        }
        ulonglong2 e;
        e.x = pk2(g0, g1); e.y = pk2(g2, g3);
        sGM[d] = e;
    }
    __syncthreads();

    // ---- epilogue: out = gm @ W2 + b2 + time ----
    if (t < 128) {
        int d = t;
        u64 o01 = 0, o23 = 0;
        #pragma unroll 4
        for (int c = 0; c < 128; c++) {
            ulonglong2 g = sGM[c];
            float w = __ldg(&W2[c*Dcst + d]);
            u64 ws = pk2(w, w);
            o01 = fma2(g.x, ws, o01);
            o23 = fma2(g.y, ws, o23);
        }
        float o0, o1, o2, o3;
        upk2(o01, o0, o1); upk2(o23, o2, o3);
        float tval = tcb[d];
        #pragma unroll
        for (int k = 0; k < 4; k++) {
            tval += g_hpro[(k*48 + sIdxH[k])*Dcst + d];
            tval += g_wpro[(k*7  + sIdxW[k])*Dcst + d];
        }
        long ob  = ((long)(n*192 + tp*4))*Dcst + d;
        long obh = OUTHALF + ob;
        out[obh] = tval; out[obh+128] = tval; out[obh+256] = tval; out[obh+384] = tval;
        float base = tval + b2[d];
        out[ob]     = o0 + base;
        out[ob+128] = o1 + base;
        out[ob+256] = o2 + base;
        out[ob+384] = o3 + base;
    }
}

// ---------------- launch ----------------
extern "C" void kernel_launch(void* const* d_in, const int* in_sizes, int n_in,
                              void* d_out, int out_size) {
    const float* x    = (const float*)d_in[0];
    const void*  xm   = d_in[1];
    const void*  ed   = d_in[2];
    const void*  ns   = d_in[3];
    const float* hemb = (const float*)d_in[4];
    const float* wemb = (const float*)d_in[5];
    const float* tcw  = (const float*)d_in[6];
    const float* tcb  = (const float*)d_in[7];
    const float* tvw  = (const float*)d_in[8];
    const float* tvb  = (const float*)d_in[9];
    const float* W1   = (const float*)d_in[10];
    const float* b1   = (const float*)d_in[11];
    const float* W2   = (const float*)d_in[12];
    const float* b2   = (const float*)d_in[13];
    float* out = (float*)d_out;

    k1<<<4 + NBcst/2, 512>>>(ed, ns, x, tvw, tvb, W1);
    k2<<<50, 512>>>(ed, tcw, hemb, wemb);
    k3<<<NBcst, 256>>>(xm, tcb, b1, W2, b2, out);
}

// round 10
// speedup vs baseline: 1.0044x; 1.0044x over previous
#include <cuda_runtime.h>
#include <cuda_bf16.h>

#define Hcst   1024
#define Dcst   128
#define TPcst  48
#define NBcst  384
#define Ecst   16384
#define EHcst  17408
#define OUTHALF 196608
#define MAXDEG 64

typedef unsigned long long u64;

// ---------------- device scratch ----------------
__device__ u64      g_Xh[NBcst*Hcst];     // 3.1 MB bf16x4 taps
__device__ int      g_cnt2[Hcst];         // degree counter: zero at load; k3 re-zeroes
__device__ int      g_cursor[Hcst];       // fill cursor: zeroed by k1
__device__ int      g_degi[Hcst];         // copy of counts (k2) for k3
__device__ unsigned g_pkT[MAXDEG*Hcst];   // transposed edges: [e][v]
__device__ float    g_rowsum[Hcst];
__device__ float    g_S[4*Hcst];
__device__ int      g_invgrp[Hcst];
__device__ float    g_WW1[4*Dcst];
__device__ float    g_bb1[Dcst];
__device__ float    g_hpro[4*48*Dcst];
__device__ float    g_wpro[4*7*Dcst];

// ---------------- helpers ----------------
__device__ __forceinline__ u64 pk2(float lo, float hi) {
    u64 r; asm("mov.b64 %0,{%1,%2};" : "=l"(r) : "f"(lo), "f"(hi)); return r;
}
__device__ __forceinline__ void upk2(u64 v, float& lo, float& hi) {
    asm("mov.b64 {%0,%1},%2;" : "=f"(lo), "=f"(hi) : "l"(v));
}
__device__ __forceinline__ u64 fma2(u64 a, u64 b, u64 c) {
    u64 d; asm("fma.rn.f32x2 %0,%1,%2,%3;" : "=l"(d) : "l"(a), "l"(b), "l"(c)); return d;
}
__device__ __forceinline__ u64 pkbf4(float a, float b, float c, float d) {
    return (u64)__bfloat16_as_ushort(__float2bfloat16(a))
         | ((u64)__bfloat16_as_ushort(__float2bfloat16(b)) << 16)
         | ((u64)__bfloat16_as_ushort(__float2bfloat16(c)) << 32)
         | ((u64)__bfloat16_as_ushort(__float2bfloat16(d)) << 48);
}

// ================= k1 : parallel degree count + prep + X4 transpose =================
__global__ void __launch_bounds__(512) k1(const void* ed, const void* ns,
        const float* x, const float* tvw, const float* tvb, const float* W1) {
    __shared__ int sflag;
    int t = threadIdx.x, blk = blockIdx.x;
    if (blk < 32) {
        // edge degree count: 32 blocks x 512 edges, GLOBAL atomics (distributed L2)
        if (t == 0) sflag = 1;
        __syncthreads();
        if (t < 64) { if (((const int*)ed)[2*t+1] != 0) atomicAnd(&sflag, 0); }
        __syncthreads();
        int f = sflag;
        int i = blk*512 + t;
        int d = f ? (int)((const long long*)ed)[2L*i+1] : ((const int*)ed)[2*i+1];
        atomicAdd(&g_cnt2[d], 1);
    } else if (blk == 32) {
        // self loops + cursor zero
        atomicAdd(&g_cnt2[t], 1);
        atomicAdd(&g_cnt2[t+512], 1);
        g_cursor[t] = 0; g_cursor[t+512] = 0;
    } else if (blk == 33) {
        if (t == 0) sflag = 1;
        __syncthreads();
        if (t < 64) { if (((const int*)ns)[2*t+1] != 0) atomicAnd(&sflag, 0); }
        __syncthreads();
        int f = sflag;
        #pragma unroll
        for (int r = 0; r < 2; r++) {
            int i = t + r*512;
            int v = f ? (int)((const long long*)ns)[i] : ((const int*)ns)[i];
            g_invgrp[v] = i >> 8;
        }
    } else if (blk == 34) {
        int k = t >> 7, e = t & 127;
        float acc = 0.f;
        for (int d = 0; d < Dcst; d++) acc += tvw[d*4 + k] * W1[d*Dcst + e];
        g_WW1[k*Dcst + e] = acc;
        if (t < 128) {
            float bsum = 0.f;
            for (int d = 0; d < Dcst; d++) bsum += tvb[d] * W1[d*Dcst + t];
            g_bb1[t] = bsum;
        }
    } else if (blk == 35) {
        #pragma unroll
        for (int i = t; i < 4*Hcst; i += 512) g_S[i] = 0.f;
        #pragma unroll
        for (int i = t; i < Hcst; i += 512) g_rowsum[i] = 0.f;
    } else {
        // X4 transpose -> bf16x4, 2 b's per block
        int sub = t >> 8, tl = t & 255;
        int b = (blk - 36)*2 + sub, n = b / TPcst, tp = b % TPcst;
        const float4* xb = (const float4*)(x + ((long)(n*192 + tp*4))*Hcst);
        float4 r0 = xb[tl], r1 = xb[256+tl], r2 = xb[512+tl], r3 = xb[768+tl];
        ulonglong2 w0, w1;
        w0.x = pkbf4(r0.x, r1.x, r2.x, r3.x);
        w0.y = pkbf4(r0.y, r1.y, r2.y, r3.y);
        w1.x = pkbf4(r0.z, r1.z, r2.z, r3.z);
        w1.y = pkbf4(r0.w, r1.w, r2.w, r3.w);
        ulonglong2* dst = (ulonglong2*)(g_Xh + (long)b*Hcst + tl*4);
        dst[0] = w0;
        dst[1] = w1;
    }
}

// ================= k2 : edge fill + projection tables + degi copy =================
__global__ void __launch_bounds__(512) k2(const void* ed,
        const float* tcw, const float* hemb, const float* wemb) {
    __shared__ union {
        int dummy;
        struct { float tcwS[8][516]; float embH[48][129]; float embW[7][129]; } p;
    } sm;
    __shared__ int sflag;
    int t = threadIdx.x, blk = blockIdx.x;
    if (blk < 34) {
        // fill pkT (+rowsum, +S): 34 x 512 = 17408
        if (t == 0) sflag = 1;
        __syncthreads();
        if (t < 64) { if (((const int*)ed)[2*t+1] != 0) atomicAnd(&sflag, 0); }
        __syncthreads();
        int f = sflag;
        int i = blk*512 + t;
        int s, d;
        if (i < Ecst) {
            if (f) { s = (int)((const long long*)ed)[2L*i]; d = (int)((const long long*)ed)[2L*i+1]; }
            else   { s = ((const int*)ed)[2*i];             d = ((const int*)ed)[2*i+1]; }
        } else s = d = i - Ecst;
        float w = rsqrtf((float)g_cnt2[s] * (float)g_cnt2[d]);
        int local = atomicAdd(&g_cursor[d], 1);
        unsigned cb = (unsigned)__bfloat16_as_ushort(__float2bfloat16(w));
        if (local < MAXDEG)
            g_pkT[local*Hcst + d] = (unsigned)s | (cb << 16);
        atomicAdd(&g_rowsum[d], w);
        atomicAdd(&g_S[g_invgrp[d]*Hcst + s], w * (1.f/256.f));
    } else if (blk == 50) {
        // copy counts for k3 (k3 zeroes g_cnt2, reads g_degi)
        g_degi[t] = g_cnt2[t];
        g_degi[t+512] = g_cnt2[t+512];
    } else {
        // projection tables: 16 blocks, 8 d's each
        int d0 = (blk - 34)*8;
        for (int i = t; i < 8*512; i += 512)
            sm.p.tcwS[i >> 9][i & 511] = tcw[(long)(d0 + (i >> 9))*512 + (i & 511)];
        for (int i = t; i < 48*128; i += 512)
            sm.p.embH[i >> 7][i & 127] = hemb[i];
        for (int i = t; i < 7*128; i += 512)
            sm.p.embW[i >> 7][i & 127] = wemb[i];
        __syncthreads();
        int dl = t & 7;
        #pragma unroll
        for (int pass = 0; pass < 4; pass++) {
            int pair = (t >> 3) + pass*64;
            if (pair >= 220) continue;
            const float* er; float* dst; int k, r;
            if (pair < 192) { k = pair / 48; r = pair % 48; er = sm.p.embH[r]; dst = g_hpro + (k*48 + r)*Dcst; }
            else { int q = pair - 192; k = q / 7; r = q % 7; er = sm.p.embW[r]; dst = g_wpro + (k*7 + r)*Dcst; }
            float acc = 0.f;
            #pragma unroll 8
            for (int c = 0; c < 128; c++)
                acc += er[c] * sm.p.tcwS[dl][4*c + k];
            dst[d0 + dl] = acc;
        }
    }
}

// ================= k3 : per-b gather + token + epilogue =================
__global__ void __launch_bounds__(256, 3) k3(const void* xm, const float* tcb,
        const float* b1, const float* W2, const float* b2, float* out) {
    __shared__ union { u64 Xh[Hcst]; float AccF[256][9]; } sm;   // 9.2 KB
    __shared__ __align__(16) float sY0[Hcst], sY1[Hcst], sY2[Hcst], sY3[Hcst]; // 16 KB
    __shared__ ulonglong2 sS01[512];     // 8 KB  (pk(S0 vpair), pk(S1 vpair))
    __shared__ ulonglong2 sS23[512];     // 8 KB
    __shared__ u64        sRSp[512];     // 4 KB
    __shared__ ulonglong2 sGM[128];      // 2 KB
    __shared__ int        sIdxH[4], sIdxW[4], sflag;

    int t = threadIdx.x, b = blockIdx.x;
    int n = b / TPcst, tp = b % TPcst;

    // block 0 resets the degree counters for the next replay (no k3 block reads g_cnt2)
    if (b == 0) {
        #pragma unroll
        for (int r = 0; r < 4; r++) g_cnt2[t + r*256] = 0;
    }

    if (t == 0) sflag = 1;
    __syncthreads();
    if (t < 64) { if (((const int*)xm)[2*t+1] != 0) atomicAnd(&sflag, 0); }

    // prefetch packed S / rowsum into registers (committed after gather)
    u64 s0p[2], s1p[2], s2p[2], s3p[2], rsp[2];
    #pragma unroll
    for (int it = 0; it < 2; it++) {
        int vp = t + it*256;
        s0p[it] = *(const u64*)&g_S[0*Hcst + 2*vp];
        s1p[it] = *(const u64*)&g_S[1*Hcst + 2*vp];
        s2p[it] = *(const u64*)&g_S[2*Hcst + 2*vp];
        s3p[it] = *(const u64*)&g_S[3*Hcst + 2*vp];
        rsp[it] = *(const u64*)&g_rowsum[2*vp];
    }
    // taps into smem
    #pragma unroll
    for (int it = 0; it < 4; it++) {
        int i = t + it*256;
        sm.Xh[i] = g_Xh[(long)b*Hcst + i];
    }
    __syncthreads();
    if (t < 8) {
        int k = t & 3, isH = t >> 2;
        long base = ((long)(n*192 + tp*4 + k))*2 + isH;
        int v = sflag ? (int)((const long long*)xm)[base] : ((const int*)xm)[base];
        if (isH) sIdxH[k] = v; else sIdxW[k] = v;
    }

    // ---- gather: 4 v's interleaved in one e-loop -> MLP 4 ----
    {
        int dv0 = g_degi[t], dv1 = g_degi[t+256], dv2 = g_degi[t+512], dv3 = g_degi[t+768];
        int dmax = max(max(dv0, dv1), max(dv2, dv3));
        float a0[4] = {0,0,0,0}, a1[4] = {0,0,0,0}, a2[4] = {0,0,0,0}, a3[4] = {0,0,0,0};
        for (int e = 0; e < dmax; e++) {
            const unsigned* row = g_pkT + e*Hcst + t;
            // inactive lanes load packed word 0 -> coef 0.0f -> no contribution
            unsigned p0 = (e < dv0) ? __ldg(&row[0])   : 0u;
            unsigned p1 = (e < dv1) ? __ldg(&row[256]) : 0u;
            unsigned p2 = (e < dv2) ? __ldg(&row[512]) : 0u;
            unsigned p3 = (e < dv3) ? __ldg(&row[768]) : 0u;
            #define GSTEP(p, acc) { \
                u64 xv = sm.Xh[(p) & 1023u]; \
                float w = __uint_as_float((p) & 0xFFFF0000u); \
                acc[0] += w*__uint_as_float((unsigned)(xv & 0xFFFFu) << 16); \
                acc[1] += w*__uint_as_float((unsigned)xv & 0xFFFF0000u); \
                acc[2] += w*__uint_as_float((unsigned)((xv >> 32) & 0xFFFFu) << 16); \
                acc[3] += w*__uint_as_float((unsigned)(xv >> 48) << 16); }
            GSTEP(p0, a0) GSTEP(p1, a1) GSTEP(p2, a2) GSTEP(p3, a3)
            #undef GSTEP
        }
        sY0[t]     = a0[0]; sY1[t]     = a0[1]; sY2[t]     = a0[2]; sY3[t]     = a0[3];
        sY0[t+256] = a1[0]; sY1[t+256] = a1[1]; sY2[t+256] = a1[2]; sY3[t+256] = a1[3];
        sY0[t+512] = a2[0]; sY1[t+512] = a2[1]; sY2[t+512] = a2[2]; sY3[t+512] = a2[3];
        sY0[t+768] = a3[0]; sY1[t+768] = a3[1]; sY2[t+768] = a3[2]; sY3[t+768] = a3[3];
    }
    // commit prefetched packed S / rowsum
    #pragma unroll
    for (int it = 0; it < 2; it++) {
        int vp = t + it*256;
        ulonglong2 e01, e23;
        e01.x = s0p[it]; e01.y = s1p[it];
        e23.x = s2p[it]; e23.y = s3p[it];
        sS01[vp] = e01; sS23[vp] = e23;
        sRSp[vp] = rsp[it];
    }
    __syncthreads();

    // ---- token loop: accumulators packed over v-parity ----
    int dA = t & 63, dB = dA + 64;
    int q  = t >> 6;
    u64 W0A = pk2(g_WW1[dA],     g_WW1[dA]);
    u64 W1A = pk2(g_WW1[128+dA], g_WW1[128+dA]);
    u64 W2A = pk2(g_WW1[256+dA], g_WW1[256+dA]);
    u64 W3A = pk2(g_WW1[384+dA], g_WW1[384+dA]);
    u64 BBA = pk2(g_bb1[dA],     g_bb1[dA]);
    u64 B1A = pk2(b1[dA],        b1[dA]);
    u64 W0B = pk2(g_WW1[dB],     g_WW1[dB]);
    u64 W1B = pk2(g_WW1[128+dB], g_WW1[128+dB]);
    u64 W2B = pk2(g_WW1[256+dB], g_WW1[256+dB]);
    u64 W3B = pk2(g_WW1[384+dB], g_WW1[384+dB]);
    u64 BBB = pk2(g_bb1[dB],     g_bb1[dB]);
    u64 B1B = pk2(b1[dB],        b1[dB]);
    u64 aA0 = 0, aA1 = 0, aA2 = 0, aA3 = 0;
    u64 aB0 = 0, aB1 = 0, aB2 = 0, aB3 = 0;
    int vp0 = q*128;
    #pragma unroll 2
    for (int vp = vp0; vp < vp0+128; vp++) {
        u64 yax = *(const u64*)&sY0[2*vp];
        u64 yay = *(const u64*)&sY1[2*vp];
        u64 ybx = *(const u64*)&sY2[2*vp];
        u64 yby = *(const u64*)&sY3[2*vp];
        u64 rp  = sRSp[vp];
        u64 hA = fma2(yax, W0A, B1A);
        hA = fma2(yay, W1A, hA);
        hA = fma2(ybx, W2A, hA);
        hA = fma2(yby, W3A, hA);
        hA = fma2(rp,  BBA, hA);
        u64 hB = fma2(yax, W0B, B1B);
        hB = fma2(yay, W1B, hB);
        hB = fma2(ybx, W2B, hB);
        hB = fma2(yby, W3B, hB);
        hB = fma2(rp,  BBB, hB);
        float ae, ao, be, bo;
        upk2(hA, ae, ao); upk2(hB, be, bo);
        u64 hAp = pk2(fmaxf(ae, 0.f), fmaxf(ao, 0.f));
        u64 hBp = pk2(fmaxf(be, 0.f), fmaxf(bo, 0.f));
        ulonglong2 s01 = sS01[vp], s23 = sS23[vp];
        aA0 = fma2(s01.x, hAp, aA0);
        aA1 = fma2(s01.y, hAp, aA1);
        aA2 = fma2(s23.x, hAp, aA2);
        aA3 = fma2(s23.y, hAp, aA3);
        aB0 = fma2(s01.x, hBp, aB0);
        aB1 = fma2(s01.y, hBp, aB1);
        aB2 = fma2(s23.x, hBp, aB2);
        aB3 = fma2(s23.y, hBp, aB3);
    }
    __syncthreads();   // Xh dead; reuse as AccF
    {
        float lo, hi;
        upk2(aA0, lo, hi); sm.AccF[t][0] = lo + hi;
        upk2(aA1, lo, hi); sm.AccF[t][1] = lo + hi;
        upk2(aA2, lo, hi); sm.AccF[t][2] = lo + hi;
        upk2(aA3, lo, hi); sm.AccF[t][3] = lo + hi;
        upk2(aB0, lo, hi); sm.AccF[t][4] = lo + hi;
        upk2(aB1, lo, hi); sm.AccF[t][5] = lo + hi;
        upk2(aB2, lo, hi); sm.AccF[t][6] = lo + hi;
        upk2(aB3, lo, hi); sm.AccF[t][7] = lo + hi;
    }
    __syncthreads();

    // ---- reduce quarters ----
    if (t < 128) {
        int d = t, lane = d & 63, useB = (d >> 6)*4;
        float g0=0.f, g1=0.f, g2=0.f, g3=0.f;
        #pragma unroll
        for (int qq = 0; qq < 4; qq++) {
            g0 += sm.AccF[qq*64+lane][useB+0];
            g1 += sm.AccF[qq*64+lane][useB+1];
            g2 += sm.AccF[qq*64+lane][useB+2];
            g3 += sm.AccF[qq*64+lane][useB+3];
        }
        ulonglong2 e;
        e.x = pk2(g0, g1); e.y = pk2(g2, g3);
        sGM[d] = e;
    }
    __syncthreads();

    // ---- epilogue: out = gm @ W2 + b2 + time ----
    if (t < 128) {
        int d = t;
        u64 o01 = 0, o23 = 0;
        #pragma unroll 4
        for (int c = 0; c < 128; c++) {
            ulonglong2 g = sGM[c];
            float w = __ldg(&W2[c*Dcst + d]);
            u64 ws = pk2(w, w);
            o01 = fma2(g.x, ws, o01);
            o23 = fma2(g.y, ws, o23);
        }
        float o0, o1, o2, o3;
        upk2(o01, o0, o1); upk2(o23, o2, o3);
        float tval = tcb[d];
        #pragma unroll
        for (int k = 0; k < 4; k++) {
            tval += g_hpro[(k*48 + sIdxH[k])*Dcst + d];
            tval += g_wpro[(k*7  + sIdxW[k])*Dcst + d];
        }
        long ob  = ((long)(n*192 + tp*4))*Dcst + d;
        long obh = OUTHALF + ob;
        out[obh] = tval; out[obh+128] = tval; out[obh+256] = tval; out[obh+384] = tval;
        float base = tval + b2[d];
        out[ob]     = o0 + base;
        out[ob+128] = o1 + base;
        out[ob+256] = o2 + base;
        out[ob+384] = o3 + base;
    }
}

// ---------------- launch ----------------
extern "C" void kernel_launch(void* const* d_in, const int* in_sizes, int n_in,
                              void* d_out, int out_size) {
    const float* x    = (const float*)d_in[0];
    const void*  xm   = d_in[1];
    const void*  ed   = d_in[2];
    const void*  ns   = d_in[3];
    const float* hemb = (const float*)d_in[4];
    const float* wemb = (const float*)d_in[5];
    const float* tcw  = (const float*)d_in[6];
    const float* tcb  = (const float*)d_in[7];
    const float* tvw  = (const float*)d_in[8];
    const float* tvb  = (const float*)d_in[9];
    const float* W1   = (const float*)d_in[10];
    const float* b1   = (const float*)d_in[11];
    const float* W2   = (const float*)d_in[12];
    const float* b2   = (const float*)d_in[13];
    float* out = (float*)d_out;

    k1<<<36 + NBcst/2, 512>>>(ed, ns, x, tvw, tvb, W1);
    k2<<<51, 512>>>(ed, tcw, hemb, wemb);
    k3<<<NBcst, 256>>>(xm, tcb, b1, W2, b2, out);
}

// round 11
// speedup vs baseline: 1.0438x; 1.0393x over previous
#include <cuda_runtime.h>
#include <cuda_bf16.h>

#define Hcst   1024
#define Dcst   128
#define TPcst  48
#define NBcst  384
#define Ecst   16384
#define EHcst  17408
#define OUTHALF 196608
#define MAXDEG 64

typedef unsigned long long u64;

// ---------------- device scratch ----------------
__device__ u64      g_Xh[NBcst*Hcst];     // 3.1 MB bf16x4 taps
__device__ int      g_cnt2[Hcst];         // degree counter: zero at load; phase C re-zeroes
__device__ int      g_cursor[Hcst];       // fill cursor: zeroed in phase A
__device__ int      g_degi[Hcst];         // copy of counts (phase B) for phase C
__device__ unsigned g_pkT[MAXDEG*Hcst];   // transposed edges: [e][v]
__device__ float    g_rowsum[Hcst];
__device__ float    g_S[4*Hcst];
__device__ int      g_invgrp[Hcst];
__device__ float    g_WW1[4*Dcst];
__device__ float    g_bb1[Dcst];
__device__ float    g_hpro[4*48*Dcst];
__device__ float    g_wpro[4*7*Dcst];
__device__ u64      g_barcnt;             // monotonic grid-barrier ticket counter

// ---------------- helpers ----------------
__device__ __forceinline__ u64 pk2(float lo, float hi) {
    u64 r; asm("mov.b64 %0,{%1,%2};" : "=l"(r) : "f"(lo), "f"(hi)); return r;
}
__device__ __forceinline__ void upk2(u64 v, float& lo, float& hi) {
    asm("mov.b64 {%0,%1},%2;" : "=f"(lo), "=f"(hi) : "l"(v));
}
__device__ __forceinline__ u64 fma2(u64 a, u64 b, u64 c) {
    u64 d; asm("fma.rn.f32x2 %0,%1,%2,%3;" : "=l"(d) : "l"(a), "l"(b), "l"(c)); return d;
}
__device__ __forceinline__ u64 pkbf4(float a, float b, float c, float d) {
    return (u64)__bfloat16_as_ushort(__float2bfloat16(a))
         | ((u64)__bfloat16_as_ushort(__float2bfloat16(b)) << 16)
         | ((u64)__bfloat16_as_ushort(__float2bfloat16(c)) << 32)
         | ((u64)__bfloat16_as_ushort(__float2bfloat16(d)) << 48);
}

// Software grid barrier: monotonic u64 ticket; all 384 blocks are wave-1
// resident (smem 47KB -> >=3 blocks/SM guaranteed by __launch_bounds__(256,3);
// 148*3=444 >= 384), so spinning is deadlock-free. Never reset -> no race.
__device__ __forceinline__ void gridbar(int t) {
    __syncthreads();
    if (t == 0) {
        __threadfence();
        u64 my = atomicAdd(&g_barcnt, 1ULL);
        u64 target = (my/NBcst + 1) * (u64)NBcst;
        while (*(volatile u64*)&g_barcnt < target) { }
        __threadfence();
    }
    __syncthreads();
}

// ================= fused kernel =================
__global__ void __launch_bounds__(256, 3) kfused(const void* ed, const void* ns,
        const void* xm, const float* x,
        const float* tcw, const float* tcb,
        const float* hemb, const float* wemb,
        const float* tvw, const float* tvb, const float* W1,
        const float* b1, const float* W2, const float* b2, float* out) {
    __shared__ union {
        struct { float tcwS[8][516]; float embH[48][129]; float embW[7][129]; } p;
        struct {
            union { u64 Xh[Hcst]; float AccF[256][9]; } xa;
            float sY0[Hcst], sY1[Hcst], sY2[Hcst], sY3[Hcst];
            ulonglong2 sS01[512], sS23[512];
            u64 sRSp[512];
            ulonglong2 sGM[128];
        } c;
    } sm;
    __shared__ int sIdxH[4], sIdxW[4], sflag;

    int t = threadIdx.x, blk = blockIdx.x;
    int b = blk, n = b / TPcst, tp = b % TPcst;

    // ================= PHASE A =================
    // every block: transpose its b's X4 -> bf16x4 (4 v's per thread)
    {
        const float4* xb = (const float4*)(x + ((long)(n*192 + tp*4))*Hcst);
        float4 r0 = xb[t], r1 = xb[256+t], r2 = xb[512+t], r3 = xb[768+t];
        ulonglong2 w0, w1;
        w0.x = pkbf4(r0.x, r1.x, r2.x, r3.x);
        w0.y = pkbf4(r0.y, r1.y, r2.y, r3.y);
        w1.x = pkbf4(r0.z, r1.z, r2.z, r3.z);
        w1.y = pkbf4(r0.w, r1.w, r2.w, r3.w);
        ulonglong2* dst = (ulonglong2*)(g_Xh + (long)b*Hcst + t*4);
        dst[0] = w0;
        dst[1] = w1;
    }
    if (blk < 64) {
        // edge degree count: 64 blocks x 256 edges (global atomics)
        if (t == 0) sflag = 1;
        __syncthreads();
        if (t < 64) { if (((const int*)ed)[2*t+1] != 0) atomicAnd(&sflag, 0); }
        __syncthreads();
        int i = blk*256 + t;
        int d = sflag ? (int)((const long long*)ed)[2L*i+1] : ((const int*)ed)[2*i+1];
        atomicAdd(&g_cnt2[d], 1);
    } else if (blk < 68) {
        int v = (blk-64)*256 + t;
        atomicAdd(&g_cnt2[v], 1);   // self loop
        g_cursor[v] = 0;
    } else if (blk < 72) {
        if (t == 0) sflag = 1;
        __syncthreads();
        if (t < 64) { if (((const int*)ns)[2*t+1] != 0) atomicAnd(&sflag, 0); }
        __syncthreads();
        int i = (blk-68)*256 + t;
        int v = sflag ? (int)((const long long*)ns)[i] : ((const int*)ns)[i];
        g_invgrp[v] = i >> 8;
    } else if (blk == 72) {
        #pragma unroll
        for (int r = 0; r < 2; r++) {
            int idx = t + r*256;
            int k = idx >> 7, e = idx & 127;
            float acc = 0.f;
            for (int d = 0; d < Dcst; d++) acc += tvw[d*4 + k] * W1[d*Dcst + e];
            g_WW1[k*Dcst + e] = acc;
        }
    } else if (blk == 73) {
        if (t < 128) {
            float bsum = 0.f;
            for (int d = 0; d < Dcst; d++) bsum += tvb[d] * W1[d*Dcst + t];
            g_bb1[t] = bsum;
        }
    } else if (blk < 78) {
        #pragma unroll
        for (int r = 0; r < 4; r++) g_S[(blk-74)*1024 + t + r*256] = 0.f;
    } else if (blk == 78) {
        #pragma unroll
        for (int r = 0; r < 4; r++) g_rowsum[t + r*256] = 0.f;
    } else if (blk >= 80 && blk < 96) {
        // projection tables: 16 blocks, 8 d's each
        int d0 = (blk - 80)*8;
        for (int i = t; i < 8*512; i += 256)
            sm.p.tcwS[i >> 9][i & 511] = tcw[(long)(d0 + (i >> 9))*512 + (i & 511)];
        for (int i = t; i < 48*128; i += 256)
            sm.p.embH[i >> 7][i & 127] = hemb[i];
        for (int i = t; i < 7*128; i += 256)
            sm.p.embW[i >> 7][i & 127] = wemb[i];
        __syncthreads();
        int dl = t & 7;
        #pragma unroll
        for (int pass = 0; pass < 7; pass++) {
            int pair = (t >> 3) + pass*32;
            if (pair >= 220) continue;
            const float* er; float* dst; int k, r;
            if (pair < 192) { k = pair / 48; r = pair % 48; er = sm.p.embH[r]; dst = g_hpro + (k*48 + r)*Dcst; }
            else { int q = pair - 192; k = q / 7; r = q % 7; er = sm.p.embW[r]; dst = g_wpro + (k*7 + r)*Dcst; }
            float acc = 0.f;
            #pragma unroll 8
            for (int c = 0; c < 128; c++)
                acc += er[c] * sm.p.tcwS[dl][4*c + k];
            dst[d0 + dl] = acc;
        }
    }
    gridbar(t);

    // ================= PHASE B : edge fill (+rowsum, +S) + degi copy =================
    if (blk < 68) {
        if (t == 0) sflag = 1;
        __syncthreads();
        if (t < 64) { if (((const int*)ed)[2*t+1] != 0) atomicAnd(&sflag, 0); }
        __syncthreads();
        int i = blk*256 + t;
        int s, d;
        if (i < Ecst) {
            if (sflag) { s = (int)((const long long*)ed)[2L*i]; d = (int)((const long long*)ed)[2L*i+1]; }
            else       { s = ((const int*)ed)[2*i];             d = ((const int*)ed)[2*i+1]; }
        } else s = d = i - Ecst;
        float w = rsqrtf((float)g_cnt2[s] * (float)g_cnt2[d]);
        int local = atomicAdd(&g_cursor[d], 1);
        unsigned cb = (unsigned)__bfloat16_as_ushort(__float2bfloat16(w));
        if (local < MAXDEG)
            g_pkT[local*Hcst + d] = (unsigned)s | (cb << 16);
        atomicAdd(&g_rowsum[d], w);
        atomicAdd(&g_S[g_invgrp[d]*Hcst + s], w * (1.f/256.f));
    } else if (blk == 68) {
        #pragma unroll
        for (int r = 0; r < 4; r++) {
            int v = t + r*256;
            g_degi[v] = g_cnt2[v];
        }
    }
    gridbar(t);

    // ================= PHASE C : per-b gather + token + epilogue =================
    // block 0 resets degree counters for the next launch (phase C reads g_degi only)
    if (blk == 0) {
        #pragma unroll
        for (int r = 0; r < 4; r++) g_cnt2[t + r*256] = 0;
    }

    if (t == 0) sflag = 1;
    __syncthreads();
    if (t < 64) { if (((const int*)xm)[2*t+1] != 0) atomicAnd(&sflag, 0); }

    // prefetch packed S / rowsum into registers (committed after gather)
    u64 s0p[2], s1p[2], s2p[2], s3p[2], rsp[2];
    #pragma unroll
    for (int it = 0; it < 2; it++) {
        int vp = t + it*256;
        s0p[it] = *(const u64*)&g_S[0*Hcst + 2*vp];
        s1p[it] = *(const u64*)&g_S[1*Hcst + 2*vp];
        s2p[it] = *(const u64*)&g_S[2*Hcst + 2*vp];
        s3p[it] = *(const u64*)&g_S[3*Hcst + 2*vp];
        rsp[it] = *(const u64*)&g_rowsum[2*vp];
    }
    // taps into smem
    #pragma unroll
    for (int it = 0; it < 4; it++) {
        int i = t + it*256;
        sm.c.xa.Xh[i] = g_Xh[(long)b*Hcst + i];
    }
    __syncthreads();
    if (t < 8) {
        int k = t & 3, isH = t >> 2;
        long base = ((long)(n*192 + tp*4 + k))*2 + isH;
        int v = sflag ? (int)((const long long*)xm)[base] : ((const int*)xm)[base];
        if (isH) sIdxH[k] = v; else sIdxW[k] = v;
    }

    // ---- gather: 4 v's interleaved in one e-loop -> MLP 4 ----
    {
        int dv0 = g_degi[t], dv1 = g_degi[t+256], dv2 = g_degi[t+512], dv3 = g_degi[t+768];
        int dmax = max(max(dv0, dv1), max(dv2, dv3));
        float a0[4] = {0,0,0,0}, a1[4] = {0,0,0,0}, a2[4] = {0,0,0,0}, a3[4] = {0,0,0,0};
        for (int e = 0; e < dmax; e++) {
            const unsigned* row = g_pkT + e*Hcst + t;
            unsigned p0 = (e < dv0) ? __ldg(&row[0])   : 0u;
            unsigned p1 = (e < dv1) ? __ldg(&row[256]) : 0u;
            unsigned p2 = (e < dv2) ? __ldg(&row[512]) : 0u;
            unsigned p3 = (e < dv3) ? __ldg(&row[768]) : 0u;
            #define GSTEP(p, acc) { \
                u64 xv = sm.c.xa.Xh[(p) & 1023u]; \
                float w = __uint_as_float((p) & 0xFFFF0000u); \
                acc[0] += w*__uint_as_float((unsigned)(xv & 0xFFFFu) << 16); \
                acc[1] += w*__uint_as_float((unsigned)xv & 0xFFFF0000u); \
                acc[2] += w*__uint_as_float((unsigned)((xv >> 32) & 0xFFFFu) << 16); \
                acc[3] += w*__uint_as_float((unsigned)(xv >> 48) << 16); }
            GSTEP(p0, a0) GSTEP(p1, a1) GSTEP(p2, a2) GSTEP(p3, a3)
            #undef GSTEP
        }
        sm.c.sY0[t]     = a0[0]; sm.c.sY1[t]     = a0[1]; sm.c.sY2[t]     = a0[2]; sm.c.sY3[t]     = a0[3];
        sm.c.sY0[t+256] = a1[0]; sm.c.sY1[t+256] = a1[1]; sm.c.sY2[t+256] = a1[2]; sm.c.sY3[t+256] = a1[3];
        sm.c.sY0[t+512] = a2[0]; sm.c.sY1[t+512] = a2[1]; sm.c.sY2[t+512] = a2[2]; sm.c.sY3[t+512] = a2[3];
        sm.c.sY0[t+768] = a3[0]; sm.c.sY1[t+768] = a3[1]; sm.c.sY2[t+768] = a3[2]; sm.c.sY3[t+768] = a3[3];
    }
    // commit prefetched packed S / rowsum
    #pragma unroll
    for (int it = 0; it < 2; it++) {
        int vp = t + it*256;
        ulonglong2 e01, e23;
        e01.x = s0p[it]; e01.y = s1p[it];
        e23.x = s2p[it]; e23.y = s3p[it];
        sm.c.sS01[vp] = e01; sm.c.sS23[vp] = e23;
        sm.c.sRSp[vp] = rsp[it];
    }
    __syncthreads();

    // ---- token loop ----
    int dA = t & 63, dB = dA + 64;
    int q  = t >> 6;
    u64 W0A = pk2(g_WW1[dA],     g_WW1[dA]);
    u64 W1A = pk2(g_WW1[128+dA], g_WW1[128+dA]);
    u64 W2A = pk2(g_WW1[256+dA], g_WW1[256+dA]);
    u64 W3A = pk2(g_WW1[384+dA], g_WW1[384+dA]);
    u64 BBA = pk2(g_bb1[dA],     g_bb1[dA]);
    u64 B1A = pk2(b1[dA],        b1[dA]);
    u64 W0B = pk2(g_WW1[dB],     g_WW1[dB]);
    u64 W1B = pk2(g_WW1[128+dB], g_WW1[128+dB]);
    u64 W2B = pk2(g_WW1[256+dB], g_WW1[256+dB]);
    u64 W3B = pk2(g_WW1[384+dB], g_WW1[384+dB]);
    u64 BBB = pk2(g_bb1[dB],     g_bb1[dB]);
    u64 B1B = pk2(b1[dB],        b1[dB]);
    u64 aA0 = 0, aA1 = 0, aA2 = 0, aA3 = 0;
    u64 aB0 = 0, aB1 = 0, aB2 = 0, aB3 = 0;
    int vp0 = q*128;
    #pragma unroll 2
    for (int vp = vp0; vp < vp0+128; vp++) {
        u64 yax = *(const u64*)&sm.c.sY0[2*vp];
        u64 yay = *(const u64*)&sm.c.sY1[2*vp];
        u64 ybx = *(const u64*)&sm.c.sY2[2*vp];
        u64 yby = *(const u64*)&sm.c.sY3[2*vp];
        u64 rp  = sm.c.sRSp[vp];
        u64 hA = fma2(yax, W0A, B1A);
        hA = fma2(yay, W1A, hA);
        hA = fma2(ybx, W2A, hA);
        hA = fma2(yby, W3A, hA);
        hA = fma2(rp,  BBA, hA);
        u64 hB = fma2(yax, W0B, B1B);
        hB = fma2(yay, W1B, hB);
        hB = fma2(ybx, W2B, hB);
        hB = fma2(yby, W3B, hB);
        hB = fma2(rp,  BBB, hB);
        float ae, ao, be, bo;
        upk2(hA, ae, ao); upk2(hB, be, bo);
        u64 hAp = pk2(fmaxf(ae, 0.f), fmaxf(ao, 0.f));
        u64 hBp = pk2(fmaxf(be, 0.f), fmaxf(bo, 0.f));
        ulonglong2 s01 = sm.c.sS01[vp], s23 = sm.c.sS23[vp];
        aA0 = fma2(s01.x, hAp, aA0);
        aA1 = fma2(s01.y, hAp, aA1);
        aA2 = fma2(s23.x, hAp, aA2);
        aA3 = fma2(s23.y, hAp, aA3);
        aB0 = fma2(s01.x, hBp, aB0);
        aB1 = fma2(s01.y, hBp, aB1);
        aB2 = fma2(s23.x, hBp, aB2);
        aB3 = fma2(s23.y, hBp, aB3);
    }
    __syncthreads();   // Xh dead; reuse as AccF
    {
        float lo, hi;
        upk2(aA0, lo, hi); sm.c.xa.AccF[t][0] = lo + hi;
        upk2(aA1, lo, hi); sm.c.xa.AccF[t][1] = lo + hi;
        upk2(aA2, lo, hi); sm.c.xa.AccF[t][2] = lo + hi;
        upk2(aA3, lo, hi); sm.c.xa.AccF[t][3] = lo + hi;
        upk2(aB0, lo, hi); sm.c.xa.AccF[t][4] = lo + hi;
        upk2(aB1, lo, hi); sm.c.xa.AccF[t][5] = lo + hi;
        upk2(aB2, lo, hi); sm.c.xa.AccF[t][6] = lo + hi;
        upk2(aB3, lo, hi); sm.c.xa.AccF[t][7] = lo + hi;
    }
    __syncthreads();

    // ---- reduce quarters ----
    if (t < 128) {
        int d = t, lane = d & 63, useB = (d >> 6)*4;
        float g0=0.f, g1=0.f, g2=0.f, g3=0.f;
        #pragma unroll
        for (int qq = 0; qq < 4; qq++) {
            g0 += sm.c.xa.AccF[qq*64+lane][useB+0];
            g1 += sm.c.xa.AccF[qq*64+lane][useB+1];
            g2 += sm.c.xa.AccF[qq*64+lane][useB+2];
            g3 += sm.c.xa.AccF[qq*64+lane][useB+3];
        }
        ulonglong2 e;
        e.x = pk2(g0, g1); e.y = pk2(g2, g3);
        sm.c.sGM[d] = e;
    }
    __syncthreads();

    // ---- epilogue: out = gm @ W2 + b2 + time ----
    if (t < 128) {
        int d = t;
        u64 o01 = 0, o23 = 0;
        #pragma unroll 4
        for (int c = 0; c < 128; c++) {
            ulonglong2 g = sm.c.sGM[c];
            float w = __ldg(&W2[c*Dcst + d]);
            u64 ws = pk2(w, w);
            o01 = fma2(g.x, ws, o01);
            o23 = fma2(g.y, ws, o23);
        }
        float o0, o1, o2, o3;
        upk2(o01, o0, o1); upk2(o23, o2, o3);
        float tval = tcb[d];
        #pragma unroll
        for (int k = 0; k < 4; k++) {
            tval += g_hpro[(k*48 + sIdxH[k])*Dcst + d];
            tval += g_wpro[(k*7  + sIdxW[k])*Dcst + d];
        }
        long ob  = ((long)(n*192 + tp*4))*Dcst + d;
        long obh = OUTHALF + ob;
        out[obh] = tval; out[obh+128] = tval; out[obh+256] = tval; out[obh+384] = tval;
        float base = tval + b2[d];
        out[ob]     = o0 + base;
        out[ob+128] = o1 + base;
        out[ob+256] = o2 + base;
        out[ob+384] = o3 + base;
    }
}

// ---------------- launch ----------------
extern "C" void kernel_launch(void* const* d_in, const int* in_sizes, int n_in,
                              void* d_out, int out_size) {
    const float* x    = (const float*)d_in[0];
    const void*  xm   = d_in[1];
    const void*  ed   = d_in[2];
    const void*  ns   = d_in[3];
    const float* hemb = (const float*)d_in[4];
    const float* wemb = (const float*)d_in[5];
    const float* tcw  = (const float*)d_in[6];
    const float* tcb  = (const float*)d_in[7];
    const float* tvw  = (const float*)d_in[8];
    const float* tvb  = (const float*)d_in[9];
    const float* W1   = (const float*)d_in[10];
    const float* b1   = (const float*)d_in[11];
    const float* W2   = (const float*)d_in[12];
    const float* b2   = (const float*)d_in[13];
    float* out = (float*)d_out;

    kfused<<<NBcst, 256>>>(ed, ns, xm, x, tcw, tcb, hemb, wemb,
                           tvw, tvb, W1, b1, W2, b2, out);
}